// round 4
// baseline (speedup 1.0000x reference)
#include <cuda_runtime.h>
#include <cuda_bf16.h>

// Problem constants
#define BDIM 2
#define CDIM 8
#define SDIM 128           // D = H = W = 128
#define BW   5.0f          // boundary weight

// total instance voxels = 2 * 4 * 128^3 = 2^24
#define NTOT (1u << 24)

__device__ double g_sum;
__device__ double g_cnt;

// 24 offsets of the L1 ball radius 2 (erosion applied twice with 6-conn cross)
__device__ __constant__ signed char OFF[24][3] = {
    {-1,0,0},{1,0,0},{0,-1,0},{0,1,0},{0,0,-1},{0,0,1},
    {-2,0,0},{2,0,0},{0,-2,0},{0,2,0},{0,0,-2},{0,0,2},
    {-1,-1,0},{-1,1,0},{1,-1,0},{1,1,0},
    {-1,0,-1},{-1,0,1},{1,0,-1},{1,0,1},
    {0,-1,-1},{0,-1,1},{0,1,-1},{0,1,1}
};

__global__ void init_kernel() {
    g_sum = 0.0;
    g_cnt = 0.0;
}

__global__ void __launch_bounds__(256)
loss_kernel(const float* __restrict__ logits,
            const float* __restrict__ targets,
            const unsigned int* __restrict__ mask,   // bool promoted to 4-byte (int32 or f32); !=0 test works for both
            const float* __restrict__ spatial)
{
    unsigned int i = blockIdx.x * 256u + threadIdx.x;   // one voxel per thread, i < 2^24

    // decode (b, c, d, h, w); w fastest -> coalesced
    int w = i & 127;
    int h = (i >> 7) & 127;
    int d = (i >> 14) & 127;
    int c = (i >> 21) & 3;         // 0..3
    int b = (i >> 23) & 1;
    int ch = 2 * c + 1;            // instance channel index in C=8

    float val = 0.0f;
    float cnt = 0.0f;

    // channel mask: nonzero word == true (handles int32 1 and float32 1.0f encodings)
    if (mask[b * CDIM + ch] != 0u) {
        // spatial mask for this (b, d, h, w)
        unsigned int sp_idx = (((unsigned)b * SDIM + d) * SDIM + h) * SDIM + w;
        float sm = __ldg(&spatial[sp_idx]);
        if (sm != 0.0f) {
            unsigned int base = ((((unsigned)b * CDIM + ch) * SDIM + d) * SDIM + h) * SDIM + w;
            float l = __ldg(&logits[base]);
            float t = __ldg(&targets[base]);

            // BCE with logits (numerically stable form)
            float bce = fmaxf(l, 0.0f) - l * t + log1pf(__expf(-fabsf(l)));

            // boundary = t - eroded ; eroded only possibly 1 when t==1
            float boundary = 0.0f;
            if (t > 0.5f) {
                int eroded = 1;
                #pragma unroll
                for (int k = 0; k < 24; ++k) {
                    int nd = d + OFF[k][0];
                    int nh = h + OFF[k][1];
                    int nw = w + OFF[k][2];
                    if ((unsigned)nd >= SDIM || (unsigned)nh >= SDIM || (unsigned)nw >= SDIM) {
                        eroded = 0; break;
                    }
                    unsigned int nidx = ((((unsigned)b * CDIM + ch) * SDIM + nd) * SDIM + nh) * SDIM + nw;
                    if (__ldg(&targets[nidx]) <= 0.5f) { eroded = 0; break; }
                }
                boundary = t - (float)eroded;
            }

            float wgt = 1.0f + (BW - 1.0f) * boundary;
            val = bce * wgt * sm;
            cnt = sm;
        }
    }

    // warp reduce
    #pragma unroll
    for (int off = 16; off > 0; off >>= 1) {
        val += __shfl_down_sync(0xFFFFFFFFu, val, off);
        cnt += __shfl_down_sync(0xFFFFFFFFu, cnt, off);
    }

    __shared__ float s_val[8];
    __shared__ float s_cnt[8];
    int lane = threadIdx.x & 31;
    int wid  = threadIdx.x >> 5;
    if (lane == 0) { s_val[wid] = val; s_cnt[wid] = cnt; }
    __syncthreads();

    if (wid == 0) {
        val = (lane < 8) ? s_val[lane] : 0.0f;
        cnt = (lane < 8) ? s_cnt[lane] : 0.0f;
        #pragma unroll
        for (int off = 4; off > 0; off >>= 1) {
            val += __shfl_down_sync(0xFFFFFFFFu, val, off);
            cnt += __shfl_down_sync(0xFFFFFFFFu, cnt, off);
        }
        if (lane == 0) {
            if (val != 0.0f) atomicAdd(&g_sum, (double)val);
            if (cnt != 0.0f) atomicAdd(&g_cnt, (double)cnt);
        }
    }
}

__global__ void finalize_kernel(float* __restrict__ out) {
    double n = g_cnt;
    double s = g_sum;
    out[0] = (n > 0.0) ? (float)(s / (n > 1.0 ? n : 1.0)) : 0.0f;
}

extern "C" void kernel_launch(void* const* d_in, const int* in_sizes, int n_in,
                              void* d_out, int out_size) {
    const float*        logits  = (const float*)d_in[0];
    const float*        targets = (const float*)d_in[1];
    const unsigned int* mask    = (const unsigned int*)d_in[2];
    const float*        spatial = (const float*)d_in[3];
    float*              out     = (float*)d_out;

    init_kernel<<<1, 1>>>();
    loss_kernel<<<NTOT / 256, 256>>>(logits, targets, mask, spatial);
    finalize_kernel<<<1, 1>>>(out);
}

// round 5
// speedup vs baseline: 2.4057x; 2.4057x over previous
#include <cuda_runtime.h>
#include <cuda_bf16.h>

#define SDIM 128
#define CDIM 8
#define ROWS_PER_SLAB 16384          // 128*128 (d,h) rows per channel slab
#define WORDS_PER_SLAB 65536         // 128^3 / 32
#define NPACK_TASKS (1u << 19)       // total 32-bit words = 2^24/32
#define NTASK2 (1u << 22)            // pass-2 tasks: 4 voxels each
#define NBLK2 4096

__device__ double g_sum;
__device__ double g_cnt;
__device__ uint4 g_pack[8 * ROWS_PER_SLAB];   // 2 MB bitmask: 1 uint4 = one 128-voxel row

__global__ void init_kernel() { g_sum = 0.0; g_cnt = 0.0; }

// ---------- 128-bit row ops (bit w = word[w>>5] bit (w&31)) ----------
__device__ __forceinline__ uint4 band(uint4 a, uint4 b) {
    return make_uint4(a.x & b.x, a.y & b.y, a.z & b.z, a.w & b.w);
}
__device__ __forceinline__ uint4 shl1(uint4 a) {   // bit w -> w+1
    return make_uint4(a.x << 1, __funnelshift_l(a.x, a.y, 1),
                      __funnelshift_l(a.y, a.z, 1), __funnelshift_l(a.z, a.w, 1));
}
__device__ __forceinline__ uint4 shr1(uint4 a) {   // bit w -> w-1
    return make_uint4(__funnelshift_r(a.x, a.y, 1), __funnelshift_r(a.y, a.z, 1),
                      __funnelshift_r(a.z, a.w, 1), a.w >> 1);
}
__device__ __forceinline__ uint4 shl2(uint4 a) {
    return make_uint4(a.x << 2, __funnelshift_l(a.x, a.y, 2),
                      __funnelshift_l(a.y, a.z, 2), __funnelshift_l(a.z, a.w, 2));
}
__device__ __forceinline__ uint4 shr2(uint4 a) {
    return make_uint4(__funnelshift_r(a.x, a.y, 2), __funnelshift_r(a.y, a.z, 2),
                      __funnelshift_r(a.z, a.w, 2), a.w >> 2);
}
// r AND (r shifted +/-1 in w): rows at L1-distance 1 in (d,h)
__device__ __forceinline__ uint4 S1(uint4 a) { return band(a, band(shl1(a), shr1(a))); }

__device__ __forceinline__ unsigned pick(uint4 v, int s) {
    unsigned lo = (s & 1) ? v.y : v.x;
    unsigned hi = (s & 1) ? v.w : v.z;
    return (s & 2) ? hi : lo;
}

// ---------- Pass 1: bit-pack targets for active channels ----------
__global__ void __launch_bounds__(256)
pack_kernel(const float* __restrict__ targets,
            const unsigned int* __restrict__ mask)
{
    unsigned j = blockIdx.x * 256u + threadIdx.x;   // word index, < 2^19
    int slab = j >> 16;                              // 0..7
    int b = slab >> 2;
    int ch = ((slab & 3) << 1) + 1;
    if (mask[b * CDIM + ch] == 0u) return;           // inactive: never read later

    unsigned jin = j & (WORDS_PER_SLAB - 1);
    size_t base = ((size_t)(b * CDIM + ch) << 21) + ((size_t)jin << 5);

    unsigned bits = 0;
    #pragma unroll
    for (int k = 0; k < 8; ++k) {
        float4 v = __ldg((const float4*)(targets + base + k * 4));
        bits |= (v.x > 0.5f ? 1u : 0u) << (4 * k + 0);
        bits |= (v.y > 0.5f ? 1u : 0u) << (4 * k + 1);
        bits |= (v.z > 0.5f ? 1u : 0u) << (4 * k + 2);
        bits |= (v.w > 0.5f ? 1u : 0u) << (4 * k + 3);
    }
    ((unsigned*)g_pack)[j] = bits;
}

// ---------- Pass 2: BCE + erosion-from-bitmask + reduction ----------
__global__ void __launch_bounds__(256)
loss_kernel(const float* __restrict__ logits,
            const unsigned int* __restrict__ mask,
            const float* __restrict__ spatial)
{
    float vsum = 0.0f, csum = 0.0f;

    for (unsigned task = blockIdx.x * 256u + threadIdx.x; task < NTASK2;
         task += NBLK2 * 256u)
    {
        int slab = task >> 19;
        int b = slab >> 2;
        int ch = ((slab & 3) << 1) + 1;
        if (mask[b * CDIM + ch] == 0u) continue;

        int lane = task & 31;                 // which float4 within the row
        int rr = (task >> 5) & (ROWS_PER_SLAB - 1);   // d*128 + h
        int d = rr >> 7, h = rr & 127;
        int w0 = lane << 2;

        // independent vector loads: logits + spatial (issued back-to-back)
        size_t lix = ((size_t)(b * CDIM + ch) << 21) + ((size_t)rr << 7) + w0;
        float4 lg = __ldg((const float4*)(logits + lix));
        unsigned six = ((unsigned)b << 21) + ((unsigned)rr << 7) + w0;
        float4 sm = __ldg((const float4*)(spatial + six));

        const uint4* pk = g_pack + slab * ROWS_PER_SLAB;
        uint4 m00 = __ldg(pk + rr);
        unsigned tw = pick(m00, lane >> 3) >> (w0 & 31);   // 4 target bits in low nibble

        // double 6-conn erosion == erosion by L1-ball radius 2 (zero-padded)
        unsigned ebits = 0;
        if (d >= 2 && d <= 125 && h >= 2 && h <= 125) {    // warp-uniform branch
            uint4 e = band(m00, band(band(shl1(m00), shr1(m00)),
                                     band(shl2(m00), shr2(m00))));
            e = band(e, S1(__ldg(pk + rr + 128)));   // d+1
            e = band(e, S1(__ldg(pk + rr - 128)));   // d-1
            e = band(e, S1(__ldg(pk + rr + 1)));     // h+1
            e = band(e, S1(__ldg(pk + rr - 1)));     // h-1
            e = band(e, __ldg(pk + rr + 256));       // d+2
            e = band(e, __ldg(pk + rr - 256));       // d-2
            e = band(e, __ldg(pk + rr + 2));         // h+2
            e = band(e, __ldg(pk + rr - 2));         // h-2
            e = band(e, __ldg(pk + rr + 129));       // d+1,h+1
            e = band(e, __ldg(pk + rr + 127));       // d+1,h-1
            e = band(e, __ldg(pk + rr - 127));       // d-1,h+1
            e = band(e, __ldg(pk + rr - 129));       // d-1,h-1
            ebits = pick(e, lane >> 3) >> (w0 & 31);
        }

        #pragma unroll
        for (int k = 0; k < 4; ++k) {
            float l = (k == 0) ? lg.x : (k == 1) ? lg.y : (k == 2) ? lg.z : lg.w;
            float s = (k == 0) ? sm.x : (k == 1) ? sm.y : (k == 2) ? sm.z : sm.w;
            unsigned tb = (tw >> k) & 1u;
            unsigned bb = tb & (((ebits >> k) & 1u) ^ 1u);   // boundary bit
            float t = (float)tb;
            float u = __expf(-fabsf(l));
            float bce = fmaxf(l, 0.0f) - l * t + __logf(1.0f + u);
            float wgt = 1.0f + 4.0f * (float)bb;
            vsum += bce * wgt * s;
            csum += s;
        }
    }

    // warp reduce
    #pragma unroll
    for (int off = 16; off > 0; off >>= 1) {
        vsum += __shfl_down_sync(0xFFFFFFFFu, vsum, off);
        csum += __shfl_down_sync(0xFFFFFFFFu, csum, off);
    }
    __shared__ float s_v[8], s_c[8];
    int lane = threadIdx.x & 31, wid = threadIdx.x >> 5;
    if (lane == 0) { s_v[wid] = vsum; s_c[wid] = csum; }
    __syncthreads();
    if (wid == 0) {
        vsum = (lane < 8) ? s_v[lane] : 0.0f;
        csum = (lane < 8) ? s_c[lane] : 0.0f;
        #pragma unroll
        for (int off = 4; off > 0; off >>= 1) {
            vsum += __shfl_down_sync(0xFFFFFFFFu, vsum, off);
            csum += __shfl_down_sync(0xFFFFFFFFu, csum, off);
        }
        if (lane == 0) {
            if (vsum != 0.0f) atomicAdd(&g_sum, (double)vsum);
            if (csum != 0.0f) atomicAdd(&g_cnt, (double)csum);
        }
    }
}

__global__ void finalize_kernel(float* __restrict__ out) {
    double n = g_cnt;
    double s = g_sum;
    out[0] = (n > 0.0) ? (float)(s / (n > 1.0 ? n : 1.0)) : 0.0f;
}

extern "C" void kernel_launch(void* const* d_in, const int* in_sizes, int n_in,
                              void* d_out, int out_size) {
    const float*        logits  = (const float*)d_in[0];
    const float*        targets = (const float*)d_in[1];
    const unsigned int* mask    = (const unsigned int*)d_in[2];
    const float*        spatial = (const float*)d_in[3];
    float*              out     = (float*)d_out;

    init_kernel<<<1, 1>>>();
    pack_kernel<<<NPACK_TASKS / 256, 256>>>(targets, mask);
    loss_kernel<<<NBLK2, 256>>>(logits, mask, spatial);
    finalize_kernel<<<1, 1>>>(out);
}